// round 1
// baseline (speedup 1.0000x reference)
#include <cuda_runtime.h>

// SlidingWindowCmn: specgram (16, 60000, 80) fp32, cmn_window=600,
// min_cmn_window=100, center=False, norm_vars=True.
//
// Window bounds (derived from torchaudio logic):
//   t <  100        : [0, 100)        n = 100
//   100 <= t < 600  : [0, t+1)        n = t+1
//   t >= 600        : [t-600, t+1)    n = 601
//
// out[t] = (x[t] - mean) * rsqrt(sumsq/n - mean^2)

namespace {
constexpr int kB      = 16;
constexpr int kT      = 60000;
constexpr int kF      = 80;
constexpr int kWin    = 600;
constexpr int kMinWin = 100;
constexpr int kL      = 2000;            // rows emitted per walker
constexpr int kNCh    = kT / kL;         // 30 chunks per batch
constexpr float kInvW = 1.0f / 601.0f;
constexpr int kPF     = 56;              // far L2-prefetch lead (rows) beyond ring
}

__global__ void __launch_bounds__(kF, 4)
cmn_kernel(const float* __restrict__ x, float* __restrict__ out)
{
    const int f = threadIdx.x;                 // feature lane, 0..79
    const int c = blockIdx.x % kNCh;           // chunk index within batch
    const int b = blockIdx.x / kNCh;           // batch

    const float* xb = x   + (size_t)b * kT * kF + f;
    float*       ob = out + (size_t)b * kT * kF + f;

    // last walker of last batch must not far-prefetch past the allocation
    const bool canPF = (blockIdx.x != (kB * kNCh - 1));

    float s = 0.f, ss = 0.f;
    int tStart, cnt;

    if (c == 0) {
        // ---- phase A: accumulate rows [0, 100) ----
        #pragma unroll 4
        for (int t = 0; t < kMinWin; ++t) {
            float v = __ldg(xb + t * kF);
            s += v;
            ss = __fmaf_rn(v, v, ss);
        }
        // ---- phase B: emit t in [0, 100) with fixed stats ----
        {
            const float inv  = 1.0f / (float)kMinWin;
            const float mean = s * inv;
            const float var  = __fmaf_rn(-mean, mean, ss * inv);
            const float rstd = rsqrtf(var);
            #pragma unroll 4
            for (int t = 0; t < kMinWin; ++t) {
                float v = __ldg(xb + t * kF);   // hot in L1
                ob[t * kF] = (v - mean) * rstd;
            }
        }
        // ---- phase C: growing window, t in [100, 600) ----
        #pragma unroll 4
        for (int t = kMinWin; t < kWin; ++t) {
            float v = __ldg(xb + t * kF);
            s += v;
            ss = __fmaf_rn(v, v, ss);
            const float inv  = __fdividef(1.0f, (float)(t + 1));
            const float mean = s * inv;
            const float var  = __fmaf_rn(-mean, mean, ss * inv);
            const float rstd = rsqrtf(var);
            ob[t * kF] = (v - mean) * rstd;
        }
        tStart = kWin;          // steady begins at t=600
        cnt    = kL - kWin;     // 1400 rows
    } else {
        // ---- warmup: 601 rows [t0-601, t0) so steady loop can subtract
        //      uniformly at every step ----
        const int t0    = c * kL;
        const int wbase = t0 - (kWin + 1);
        {
            float v = __ldg(xb + wbase * kF);
            s += v; ss = __fmaf_rn(v, v, ss);
        }
        const float* pw = xb + (wbase + 1) * kF;
        for (int g = 0; g < kWin / 8; ++g) {        // 75 groups of 8
            float v[8];
            #pragma unroll
            for (int u = 0; u < 8; ++u) {
                v[u] = __ldg(pw + u * kF);
                asm volatile("prefetch.global.L2 [%0];"
                             :: "l"(pw + (u + kPF) * kF));   // always in-bounds here
            }
            #pragma unroll
            for (int u = 0; u < 8; ++u) { s += v[u]; ss = __fmaf_rn(v[u], v[u], ss); }
            pw += 8 * kF;
        }
        tStart = t0;
        cnt    = kL;            // 2000 rows
    }

    // ---- steady loop: emit rows [tStart, tStart+cnt) ----
    // invariant entering step t: (s,ss) cover rows [max(0, t-601), t)
    // step: add x[t], subtract x[t-601] (0 for the virtual row -1), emit.
    float bn[8], bo[8];

    const float* pn = xb + tStart * kF;             // forward (new) stream
    #pragma unroll
    for (int u = 0; u < 8; ++u) bn[u] = __ldg(pn + u * kF);
    pn += 8 * kF;

    {   // expiring (old) stream starts at row tStart-601 (== -1 only for c==0)
        const int r0 = tStart - (kWin + 1);
        #pragma unroll
        for (int u = 0; u < 8; ++u) {
            const int r = r0 + u;
            bo[u] = (r >= 0) ? __ldcs(xb + r * kF) : 0.0f;
        }
    }
    const float* po = xb + (tStart - (kWin + 1) + 8) * kF;
    float* pout = ob + tStart * kF;

    const int mainN = cnt - 8;                      // 1392 or 1992, both %8==0
    for (int i = 0; i < mainN; i += 8) {
        #pragma unroll
        for (int u = 0; u < 8; ++u) {
            const float vn = bn[u];
            const float vo = bo[u];
            bn[u] = __ldg(pn + u * kF);             // refill ring (row t+8)
            bo[u] = __ldcs(po + u * kF);            // evict-first: L2 reuse only
            if (canPF)
                asm volatile("prefetch.global.L2 [%0];"
                             :: "l"(pn + (u + kPF) * kF));
            s += (vn - vo);
            const float d2 = __fmaf_rn(vn, vn, -(vo * vo));
            ss += d2;
            const float mean = s * kInvW;
            const float var  = __fmaf_rn(-mean, mean, ss * kInvW);
            const float rstd = rsqrtf(var);
            __stcs(pout + u * kF, (vn - mean) * rstd);  // streaming store
        }
        pn += 8 * kF; po += 8 * kF; pout += 8 * kF;
    }

    // drain: final 8 rows from the rings, no refills
    #pragma unroll
    for (int u = 0; u < 8; ++u) {
        const float vn = bn[u];
        const float vo = bo[u];
        s += (vn - vo);
        const float d2 = __fmaf_rn(vn, vn, -(vo * vo));
        ss += d2;
        const float mean = s * kInvW;
        const float var  = __fmaf_rn(-mean, mean, ss * kInvW);
        const float rstd = rsqrtf(var);
        __stcs(pout + u * kF, (vn - mean) * rstd);
    }
}

extern "C" void kernel_launch(void* const* d_in, const int* in_sizes, int n_in,
                              void* d_out, int out_size)
{
    const float* x = (const float*)d_in[0];
    float* o = (float*)d_out;
    (void)in_sizes; (void)n_in; (void)out_size;   // fixed shape (16, 60000, 80)

    cmn_kernel<<<dim3(kB * kNCh), dim3(kF)>>>(x, o);
}

// round 2
// speedup vs baseline: 1.1385x; 1.1385x over previous
#include <cuda_runtime.h>
#include <cstdint>

// SlidingWindowCmn (16, 60000, 80) fp32, window=600, min=100, center=False,
// norm_vars=True.
//
// One walker (CTA, 80 threads = 1 thread/feature) per (batch, time-chunk).
// Last 672 rows live in a SMEM ring (per-thread scratch, no syncs): the
// expiring row x[t-601] is re-read from SMEM instead of DRAM, so every input
// row is fetched from HBM exactly once. Rows stream in via cp.async 64 rows
// ahead of consumption.

namespace {
constexpr int kB       = 16;
constexpr int kT       = 60000;
constexpr int kF       = 80;
constexpr int kWin     = 600;
constexpr int kMinWin  = 100;
constexpr int kChunks  = 9;
constexpr int kL       = 6672;                // 8*6672 + 6624 = 60000
constexpr int kR       = 672;                 // ring rows (601 + 71 margin)
constexpr uint32_t kRowB = kF * 4;            // 320 bytes / row
constexpr uint32_t kRB   = kR * kRowB;        // 215040 bytes ring
constexpr int kLead    = 64;                  // cp.async lead (rows)
constexpr int kG       = 4;                   // rows per cp.async group
constexpr float kInvW  = 1.0f / 601.0f;
constexpr int kGrid    = kB * kChunks;        // 144 blocks, 1/SM
}

__device__ __forceinline__ uint32_t smem_addr(const void* p) {
    uint32_t a;
    asm("{ .reg .u64 t; cvta.to.shared.u64 t, %1; cvt.u32.u64 %0, t; }"
        : "=r"(a) : "l"(p));
    return a;
}
__device__ __forceinline__ void cp_async4(uint32_t s, const float* g) {
    asm volatile("cp.async.ca.shared.global [%0], [%1], 4;"
                 :: "r"(s), "l"(g));
}
__device__ __forceinline__ void cp_commit() {
    asm volatile("cp.async.commit_group;" ::: "memory");
}
__device__ __forceinline__ void cp_wait16() {
    asm volatile("cp.async.wait_group 16;" ::: "memory");
}
__device__ __forceinline__ float lds_f32(uint32_t a) {
    float v; asm volatile("ld.shared.f32 %0, [%1];" : "=f"(v) : "r"(a));
    return v;
}
__device__ __forceinline__ void sts_f32(uint32_t a, float v) {
    asm volatile("st.shared.f32 [%0], %1;" :: "r"(a), "f"(v));
}

__global__ void __launch_bounds__(kF, 1)
cmn_kernel(const float* __restrict__ x, float* __restrict__ out)
{
    extern __shared__ float ring[];
    const int f = threadIdx.x;                 // feature lane 0..79
    const int c = blockIdx.x % kChunks;
    const int b = blockIdx.x / kChunks;

    const float* xb   = x   + (size_t)b * kT * kF + f;
    float*       ob   = out + (size_t)b * kT * kF + f;
    const float* pLast = x + ((size_t)kB * kT - 1) * kF + f;  // clamp target

    const uint32_t rb = smem_addr(ring) + (uint32_t)f * 4u;

    const int start = c * kL;
    const int end   = (start + kL < kT) ? (start + kL) : kT;

    float s = 0.0f, ss = 0.0f;
    int t0;                                    // first pipelined row
    if (c == 0) {
        t0 = 0;
    } else {
        // scalar row start-601 (keeps pipelined counts multiples of 4)
        const int r0 = start - kWin - 1;
        float v = __ldcs(xb + (size_t)r0 * kF);
        s = v; ss = v * v;
        sts_f32(rb + (uint32_t)(r0 % kR) * kRowB, v);
        t0 = start - kWin;                     // start-600, %4 == 0
    }

    // ---- cp.async pipeline state ----
    const float* pIss  = xb + (size_t)t0 * kF;
    uint32_t     issOff = (uint32_t)(t0 % kR) * kRowB;

    // prologue: issue 16 groups (64 rows)
    #pragma unroll 1
    for (int g = 0; g < kLead / kG; ++g) {
        #pragma unroll
        for (int u = 0; u < kG; ++u) {
            const float* p = (pIss > pLast) ? pLast : pIss;
            cp_async4(rb + issOff, p);
            pIss += kF;
            issOff += kRowB; if (issOff >= kRB) issOff -= kRB;
        }
        cp_commit();
    }

    uint32_t vnOff = (uint32_t)(t0 % kR) * kRowB;

    // issue-4 + wait so the 16-groups-older rows are resident
    auto pump = [&]() {
        #pragma unroll
        for (int u = 0; u < kG; ++u) {
            const float* p = (pIss > pLast) ? pLast : pIss;
            cp_async4(rb + issOff, p);
            pIss += kF;
            issOff += kRowB; if (issOff >= kRB) issOff -= kRB;
        }
        cp_commit();
        cp_wait16();
    };

    float* po;
    int steadyGroups;

    if (c == 0) {
        // phase A: accumulate rows [0,100)
        for (int g = 0; g < kMinWin / kG; ++g) {
            pump();
            #pragma unroll
            for (int u = 0; u < kG; ++u) {
                float v = lds_f32(rb + vnOff);
                vnOff += kRowB; if (vnOff >= kRB) vnOff -= kRB;
                s += v; ss = __fmaf_rn(v, v, ss);
            }
        }
        // phase B: emit rows [0,100) with fixed stats (re-read from ring)
        {
            const float inv  = 1.0f / (float)kMinWin;
            const float mean = s * inv;
            const float var  = __fmaf_rn(-mean, mean, ss * inv);
            const float rstd = rsqrtf(var);
            po = ob;
            uint32_t o2 = rb;                  // rows 0..99 at slots 0..99
            #pragma unroll 4
            for (int r = 0; r < kMinWin; ++r) {
                float v = lds_f32(o2); o2 += kRowB;
                __stcs(po, (v - mean) * rstd); po += kF;
            }
        }
        // phase C: growing window, t in [100, 600)
        po = ob + (size_t)kMinWin * kF;
        float n = (float)kMinWin;
        for (int g = 0; g < (kWin - kMinWin) / kG; ++g) {
            pump();
            #pragma unroll
            for (int u = 0; u < kG; ++u) {
                float v = lds_f32(rb + vnOff);
                vnOff += kRowB; if (vnOff >= kRB) vnOff -= kRB;
                s += v; ss = __fmaf_rn(v, v, ss);
                n += 1.0f;
                float inv  = __fdividef(1.0f, n);
                float mean = s * inv;
                float var  = __fmaf_rn(-mean, mean, ss * inv);
                float rstd = rsqrtf(var);
                __stcs(po, (v - mean) * rstd); po += kF;
            }
        }
        // first steady group (t=600..603): t=600 subtracts virtual x[-1]=0
        {
            pump();
            #pragma unroll
            for (int u = 0; u < kG; ++u) {
                float vn = lds_f32(rb + vnOff);
                uint32_t voOff = vnOff + 71u * kRowB;
                if (voOff >= kRB) voOff -= kRB;
                float vo = (u == 0) ? 0.0f : lds_f32(rb + voOff);
                vnOff += kRowB; if (vnOff >= kRB) vnOff -= kRB;
                s += (vn - vo);
                ss += __fmaf_rn(vn, vn, -(vo * vo));
                float mean = s * kInvW;
                float var  = __fmaf_rn(-mean, mean, ss * kInvW);
                float rstd = rsqrtf(var);
                __stcs(po, (vn - mean) * rstd); po += kF;
            }
        }
        steadyGroups = (end - kWin) / kG - 1;  // 6072/4 - 1
    } else {
        // warmup: accumulate rows [start-600, start)
        for (int g = 0; g < kWin / kG; ++g) {
            pump();
            #pragma unroll
            for (int u = 0; u < kG; ++u) {
                float v = lds_f32(rb + vnOff);
                vnOff += kRowB; if (vnOff >= kRB) vnOff -= kRB;
                s += v; ss = __fmaf_rn(v, v, ss);
            }
        }
        po = ob + (size_t)start * kF;
        steadyGroups = (end - start) / kG;     // 1668 or 1656
    }

    // ---- steady sliding window ----
    for (int g = 0; g < steadyGroups; ++g) {
        pump();
        #pragma unroll
        for (int u = 0; u < kG; ++u) {
            float vn = lds_f32(rb + vnOff);                // x[t]
            uint32_t voOff = vnOff + 71u * kRowB;          // slot (t-601)%672
            if (voOff >= kRB) voOff -= kRB;
            float vo = lds_f32(rb + voOff);                // x[t-601]
            vnOff += kRowB; if (vnOff >= kRB) vnOff -= kRB;
            s += (vn - vo);
            ss += __fmaf_rn(vn, vn, -(vo * vo));
            float mean = s * kInvW;
            float var  = __fmaf_rn(-mean, mean, ss * kInvW);
            float rstd = rsqrtf(var);
            __stcs(po, (vn - mean) * rstd); po += kF;
        }
    }
}

extern "C" void kernel_launch(void* const* d_in, const int* in_sizes, int n_in,
                              void* d_out, int out_size)
{
    const float* x = (const float*)d_in[0];
    float* o = (float*)d_out;
    (void)in_sizes; (void)n_in; (void)out_size;

    cudaFuncSetAttribute(cmn_kernel,
                         cudaFuncAttributeMaxDynamicSharedMemorySize, (int)kRB);
    cmn_kernel<<<kGrid, kF, kRB>>>(x, o);
}

// round 3
// speedup vs baseline: 1.7648x; 1.5502x over previous
#include <cuda_runtime.h>
#include <cstdint>

// SlidingWindowCmn (16, 60000, 80) fp32, window=600, min=100, center=False,
// norm_vars=True.
// cp.async -> 672-row SMEM ring -> per-thread sliding window (1 thr/feature).
// All offsets amortized per 8-row group; per-thread 4B cp.async keeps
// writer==reader (no CTA barriers needed).

namespace {
constexpr int kB      = 16;
constexpr int kT      = 60000;
constexpr int kF      = 80;
constexpr int kWin    = 600;
constexpr int kMin    = 100;
constexpr int kChunks = 9;
constexpr int kL      = 6672;              // 8*6672 + 6624 = 60000
constexpr int kR      = 672;               // ring rows (mult of 8)
constexpr int kRBF    = kR * kF;           // 53760 floats
constexpr uint32_t kRBb = kR * kF * 4u;    // 215040 bytes
constexpr float kInvW = 1.0f / 601.0f;
constexpr int kGrid   = kB * kChunks;      // 144
}

__device__ __forceinline__ uint32_t smem_u32(const void* p) {
    uint32_t a;
    asm("{ .reg .u64 t; cvta.to.shared.u64 t, %1; cvt.u32.u64 %0, t; }"
        : "=r"(a) : "l"(p));
    return a;
}
__device__ __forceinline__ void cpa4(uint32_t s, const float* g) {
    asm volatile("cp.async.ca.shared.global [%0], [%1], 4;" :: "r"(s), "l"(g));
}
__device__ __forceinline__ void cpcommit() {
    asm volatile("cp.async.commit_group;" ::: "memory");
}
__device__ __forceinline__ void cpwait7() {
    asm volatile("cp.async.wait_group 7;" ::: "memory");
}

__global__ void __launch_bounds__(kF, 1)
cmn_kernel(const float* __restrict__ x, float* __restrict__ out)
{
    extern __shared__ float ring[];
    const int f = threadIdx.x;                    // feature 0..79
    const int c = blockIdx.x % kChunks;
    const int b = blockIdx.x / kChunks;

    const float* xb = x + (size_t)b * kT * kF;
    const int start = c * kL;
    const int end   = (c == kChunks - 1) ? kT : start + kL;

    const uint32_t rbf = smem_u32(ring) + (uint32_t)f * 4u;  // smem base for this lane
    const float* pClamp = x + ((size_t)kB * kT - 8) * kF + f;

    float s = 0.f, ss = 0.f, mean, qss;
    int vnF, voF;            // ring float-offsets (slot*80), lane-excluded
    uint32_t issB;           // ring byte-offset of issue group
    const float* pIss;

    if (c == 0) {
        vnF = 0; voF = 0; issB = 0;
        pIss = xb + f;
    } else {
        const int t0    = start - kWin;           // start-600
        const int slot0 = t0 % kR;
        vnF  = slot0 * kF;
        issB = (uint32_t)slot0 * 320u;
        const int voSlot = slot0 ? slot0 - 1 : kR - 1;
        voF = voSlot * kF;
        // scalar row start-601
        float v = __ldcs(xb + (size_t)(start - kWin - 1) * kF + f);
        s = v; ss = v * v;
        ring[voSlot * kF + f] = v;
        pIss = xb + (size_t)t0 * kF + f;
    }

    auto issue = [&]() {
        const float* q = (pIss > pClamp) ? pClamp : pIss;  // 1 cmp+sel / group
        const uint32_t a = rbf + issB;
        #pragma unroll
        for (int u = 0; u < 8; ++u)
            cpa4(a + (uint32_t)(u * 320), q + u * kF);
        cpcommit();
        pIss += 8 * kF;
        issB += 2560u; if (issB >= kRBb) issB -= kRBb;
    };

    // prologue: 8 groups (64 rows) in flight
    #pragma unroll 1
    for (int g = 0; g < 8; ++g) issue();

    float* po = out + (size_t)b * kT * kF + f;

    if (c == 0) {
        // groups 0..11: rows 0..95, accumulate only
        #pragma unroll 1
        for (int g = 0; g < 12; ++g) {
            cpwait7();
            #pragma unroll
            for (int u = 0; u < 8; ++u) {
                float v = ring[vnF + u * kF + f];
                s += v; ss = __fmaf_rn(v, v, ss);
            }
            vnF += 8 * kF;
            issue();
        }
        // group 12: rows 96..103
        {
            cpwait7();
            #pragma unroll
            for (int u = 0; u < 4; ++u) {          // t=96..99
                float v = ring[vnF + u * kF + f];
                s += v; ss = __fmaf_rn(v, v, ss);
            }
            {   // burst-emit rows 0..99 with fixed stats
                const float inv = 1.0f / (float)kMin;
                const float m   = s * inv;
                const float var = __fmaf_rn(-m, m, ss * inv);
                const float r   = rsqrtf(var);
                #pragma unroll 1
                for (int t = 0; t < kMin; ++t) {
                    float v = ring[t * kF + f];
                    __stcs(po + t * kF, (v - m) * r);
                }
            }
            float n = 100.0f;
            #pragma unroll
            for (int u = 4; u < 8; ++u) {          // t=100..103 growing
                float v = ring[vnF + u * kF + f];
                s += v; ss = __fmaf_rn(v, v, ss);
                n += 1.0f;
                float inv = __fdividef(1.0f, n);
                float m   = s * inv;
                float var = __fmaf_rn(-m, m, ss * inv);
                __stcs(po + (96 + u) * kF, (v - m) * rsqrtf(var));
            }
            vnF += 8 * kF;
            issue();
        }
        // groups 13..74: rows 104..599 growing window
        float n = 104.0f;
        po += 104 * kF;
        #pragma unroll 1
        for (int g = 13; g < 75; ++g) {
            cpwait7();
            #pragma unroll
            for (int u = 0; u < 8; ++u) {
                float v = ring[vnF + u * kF + f];
                s += v; ss = __fmaf_rn(v, v, ss);
                n += 1.0f;
                float inv = __fdividef(1.0f, n);
                float m   = s * inv;
                float var = __fmaf_rn(-m, m, ss * inv);
                __stcs(po + u * kF, (v - m) * rsqrtf(var));
            }
            vnF += 8 * kF;
            po  += 8 * kF;
            issue();
        }
        // switch to incremental scaled accumulators
        mean = s * kInvW; qss = ss * kInvW;
        // special group 75: rows 600..607 (t=600 subtracts virtual x[-1]=0)
        {
            cpwait7();
            #pragma unroll
            for (int u = 0; u < 8; ++u) {
                float vn = ring[vnF + u * kF + f];
                float vo = (u == 0) ? 0.0f : ring[(u - 1) * kF + f];
                mean = __fmaf_rn(vn - vo, kInvW, mean);
                qss  = __fmaf_rn(__fmaf_rn(vn, vn, -(vo * vo)), kInvW, qss);
                float var = __fmaf_rn(-mean, mean, qss);
                __stcs(po + u * kF, (vn - mean) * rsqrtf(var));
            }
            vnF += 8 * kF;
            po  += 8 * kF;
            issue();
            voF = 7 * kF;           // slot of row 7 = (608-601)
        }
    } else {
        // warmup: 75 groups, rows [start-600, start)
        #pragma unroll 1
        for (int g = 0; g < 75; ++g) {
            cpwait7();
            #pragma unroll
            for (int u = 0; u < 8; ++u) {
                float v = ring[vnF + u * kF + f];
                s += v; ss = __fmaf_rn(v, v, ss);
            }
            vnF += 8 * kF; if (vnF >= kRBF) vnF -= kRBF;
            issue();
        }
        mean = s * kInvW; qss = ss * kInvW;
        po += (size_t)start * kF;
    }

    // ---- steady sliding loop ----
    const int nSteady = (c == 0) ? (kL - kWin - 8) / 8    // 758
                                 : (end - start) / 8;     // 834 or 828
    #pragma unroll 1
    for (int g = 0; g < nSteady; ++g) {
        cpwait7();
        #pragma unroll
        for (int u = 0; u < 8; ++u) {
            float vn = ring[vnF + u * kF + f];
            int vf = voF + u * kF; if (vf >= kRBF) vf -= kRBF;
            float vo = ring[vf + f];
            mean = __fmaf_rn(vn - vo, kInvW, mean);
            qss  = __fmaf_rn(__fmaf_rn(vn, vn, -(vo * vo)), kInvW, qss);
            float var = __fmaf_rn(-mean, mean, qss);
            __stcs(po + u * kF, (vn - mean) * rsqrtf(var));
        }
        vnF += 8 * kF; if (vnF >= kRBF) vnF -= kRBF;
        voF += 8 * kF; if (voF >= kRBF) voF -= kRBF;
        po  += 8 * kF;
        issue();
    }
}

extern "C" void kernel_launch(void* const* d_in, const int* in_sizes, int n_in,
                              void* d_out, int out_size)
{
    const float* x = (const float*)d_in[0];
    float* o = (float*)d_out;
    (void)in_sizes; (void)n_in; (void)out_size;

    cudaFuncSetAttribute(cmn_kernel,
                         cudaFuncAttributeMaxDynamicSharedMemorySize, (int)kRBb);
    cmn_kernel<<<kGrid, kF, kRBb>>>(x, o);
}

// round 4
// speedup vs baseline: 1.7749x; 1.0057x over previous
#include <cuda_runtime.h>
#include <cstdint>

// SlidingWindowCmn (16, 60000, 80) fp32, window=600, min=100, center=False,
// norm_vars=True.
// cp.async -> 680-row SMEM ring (672 logical + 7-row mirror) -> per-thread
// sliding window (1 thread/feature). 16-row groups, all offsets amortized
// per group; writer==reader per thread so no CTA barriers needed.

namespace {
constexpr int kB      = 16;
constexpr int kT      = 60000;
constexpr int kF      = 80;
constexpr int kWin    = 600;
constexpr int kMin    = 100;
constexpr int kChunks = 9;
constexpr int kL      = 6672;               // 8*6672 + 6624 = 60000
constexpr int kRL     = 672;                // logical ring rows
constexpr int kRT     = 680;                // + 8 mirror rows
constexpr int kRLf    = kRL * kF;           // 53760 floats
constexpr uint32_t kRLb = kRL * 320u;       // 215040 bytes (logical)
constexpr uint32_t kRTb = kRT * 320u;       // 217600 bytes (alloc)
constexpr float kInvW = 1.0f / 601.0f;
constexpr int kGrid   = kB * kChunks;       // 144
}

__device__ __forceinline__ uint32_t smem_u32(const void* p) {
    uint32_t a;
    asm("{ .reg .u64 t; cvta.to.shared.u64 t, %1; cvt.u32.u64 %0, t; }"
        : "=r"(a) : "l"(p));
    return a;
}
__device__ __forceinline__ void cpa4(uint32_t s, const float* g) {
    asm volatile("cp.async.ca.shared.global [%0], [%1], 4;" :: "r"(s), "l"(g));
}
__device__ __forceinline__ void cpcommit() {
    asm volatile("cp.async.commit_group;" ::: "memory");
}
__device__ __forceinline__ void cpwait3() {
    asm volatile("cp.async.wait_group 3;" ::: "memory");
}

__global__ void __launch_bounds__(kF, 1)
cmn_kernel(const float* __restrict__ x, float* __restrict__ out)
{
    extern __shared__ float ring[];
    const int f = threadIdx.x;                    // feature 0..79
    const int c = blockIdx.x % kChunks;
    const int b = blockIdx.x / kChunks;

    const float* xb = x + (size_t)b * kT * kF;
    const int start = c * kL;
    const int end   = (c == kChunks - 1) ? kT : start + kL;

    const uint32_t rbf = smem_u32(ring) + (uint32_t)f * 4u;
    const float* pClamp = x + ((size_t)kB * kT - 16) * kF + f;  // last full group

    int vnF;                 // consume slot-group float offset (lane excluded)
    uint32_t issB;           // issue slot-group byte offset
    const float* pIss;

    if (c == 0) {
        vnF = 0; issB = 0;
        pIss = xb + f;
    } else {
        const int t0   = start - 608;             // 16-aligned, 7 pad + 601 warmup
        const int slot = t0 % kRL;                // multiple of 16
        vnF  = slot * kF;
        issB = (uint32_t)slot * 320u;
        pIss = xb + (size_t)t0 * kF + f;
    }

    auto issue16 = [&]() {
        const float* q = (pIss > pClamp) ? pClamp : pIss;
        const uint32_t a = rbf + issB;
        #pragma unroll
        for (int u = 0; u < 16; ++u)
            cpa4(a + (uint32_t)(u * 320), q + u * kF);
        if (issB == 0) {                          // also fill mirror 672..679
            #pragma unroll
            for (int u = 0; u < 8; ++u)
                cpa4(rbf + (uint32_t)((kRL + u) * 320), q + u * kF);
        }
        cpcommit();
        pIss += 16 * kF;
        issB += 5120u; if (issB == kRLb) issB = 0;
    };

    // prologue: 4 groups (64 rows) in flight
    issue16(); issue16(); issue16(); issue16();

    float s = 0.f, ss = 0.f, mean, qss;
    float* po = out + (size_t)b * kT * kF + f;
    int nSteady;

    if (c == 0) {
        // groups 0..5: rows 0..95 accumulate
        #pragma unroll 1
        for (int g = 0; g < 6; ++g) {
            cpwait3();
            const float* rvn = ring + vnF + f;
            #pragma unroll
            for (int u = 0; u < 16; ++u) {
                float v = rvn[u * kF];
                s += v; ss = __fmaf_rn(v, v, ss);
            }
            vnF += 16 * kF;
            issue16();
        }
        // group 6: rows 96..111
        {
            cpwait3();
            const float* rvn = ring + vnF + f;
            #pragma unroll
            for (int u = 0; u < 4; ++u) {          // rows 96..99
                float v = rvn[u * kF];
                s += v; ss = __fmaf_rn(v, v, ss);
            }
            {   // burst-emit rows 0..99 with fixed n=100 stats
                const float inv = 1.0f / (float)kMin;
                const float m   = s * inv;
                const float var = __fmaf_rn(-m, m, ss * inv);
                const float r   = rsqrtf(var);
                #pragma unroll 4
                for (int t = 0; t < kMin; ++t) {
                    float v = ring[t * kF + f];
                    __stcs(po + t * kF, (v - m) * r);
                }
            }
            float n = 100.0f;
            #pragma unroll
            for (int u = 4; u < 16; ++u) {         // rows 100..111 growing
                float v = rvn[u * kF];
                s += v; ss = __fmaf_rn(v, v, ss);
                n += 1.0f;
                float inv = __fdividef(1.0f, n);
                float m   = s * inv;
                float var = __fmaf_rn(-m, m, ss * inv);
                __stcs(po + (96 + u) * kF, (v - m) * rsqrtf(var));
            }
            vnF += 16 * kF;
            issue16();
        }
        // groups 7..36: rows 112..591 growing
        po += 112 * kF;
        float n = 112.0f;
        #pragma unroll 1
        for (int g = 7; g < 37; ++g) {
            cpwait3();
            const float* rvn = ring + vnF + f;
            #pragma unroll
            for (int u = 0; u < 16; ++u) {
                float v = rvn[u * kF];
                s += v; ss = __fmaf_rn(v, v, ss);
                n += 1.0f;
                float inv = __fdividef(1.0f, n);
                float m   = s * inv;
                float var = __fmaf_rn(-m, m, ss * inv);
                __stcs(po + u * kF, (v - m) * rsqrtf(var));
            }
            vnF += 16 * kF;
            po  += 16 * kF;
            issue16();
        }
        // group 37: rows 592..607 (transition at t=600)
        {
            cpwait3();
            const float* rvn = ring + vnF + f;
            #pragma unroll
            for (int u = 0; u < 8; ++u) {          // rows 592..599 growing
                float v = rvn[u * kF];
                s += v; ss = __fmaf_rn(v, v, ss);
                n += 1.0f;
                float inv = __fdividef(1.0f, n);
                float m   = s * inv;
                float var = __fmaf_rn(-m, m, ss * inv);
                __stcs(po + u * kF, (v - m) * rsqrtf(var));
            }
            mean = s * kInvW; qss = ss * kInvW;
            #pragma unroll
            for (int u = 8; u < 16; ++u) {         // rows 600..607 steady
                float vn = rvn[u * kF];
                float vo = (u == 8) ? 0.0f : ring[(u - 9) * kF + f];
                float d  = vn - vo;
                float t1 = d * kInvW;
                mean += t1;
                qss   = __fmaf_rn(t1, vn + vo, qss);
                float var = __fmaf_rn(-mean, mean, qss);
                __stcs(po + u * kF, (vn - mean) * rsqrtf(var));
            }
            vnF += 16 * kF;                        // = 608*kF
            po  += 16 * kF;
            issue16();
        }
        nSteady = (kL - 608) / 16;                 // 379
    } else {
        // warmup group 0: rows t0+7 .. t0+15 (start-601 .. start-593)
        {
            cpwait3();
            const float* rvn = ring + vnF + f;
            #pragma unroll
            for (int u = 7; u < 16; ++u) {
                float v = rvn[u * kF];
                s += v; ss = __fmaf_rn(v, v, ss);
            }
            vnF += 16 * kF; if (vnF == kRLf) vnF = 0;
            issue16();
        }
        // warmup groups 1..37: 592 rows
        #pragma unroll 1
        for (int g = 1; g < 38; ++g) {
            cpwait3();
            const float* rvn = ring + vnF + f;
            #pragma unroll
            for (int u = 0; u < 16; ++u) {
                float v = rvn[u * kF];
                s += v; ss = __fmaf_rn(v, v, ss);
            }
            vnF += 16 * kF; if (vnF == kRLf) vnF = 0;
            issue16();
        }
        mean = s * kInvW; qss = ss * kInvW;
        po += (size_t)start * kF;
        nSteady = (end - start) / 16;              // 417 or 414
    }

    // ---- steady sliding loop ----
    #pragma unroll 1
    for (int g = 0; g < nSteady; ++g) {
        cpwait3();
        const float* rvn = ring + vnF + f;
        int voF = vnF + 71 * kF;                   // slot (t-601), group-aligned
        if (voF >= kRLf) voF -= kRLf;              // one wrap check per 16 rows
        const float* rvo = ring + voF + f;         // mirror covers straddle
        #pragma unroll
        for (int u = 0; u < 16; ++u) {
            float vn = rvn[u * kF];
            float vo = rvo[u * kF];
            float d  = vn - vo;
            float t1 = d * kInvW;
            mean += t1;
            qss   = __fmaf_rn(t1, vn + vo, qss);
            float var = __fmaf_rn(-mean, mean, qss);
            __stcs(po + u * kF, (vn - mean) * rsqrtf(var));
        }
        vnF += 16 * kF; if (vnF == kRLf) vnF = 0;
        po  += 16 * kF;
        issue16();
    }
}

extern "C" void kernel_launch(void* const* d_in, const int* in_sizes, int n_in,
                              void* d_out, int out_size)
{
    const float* x = (const float*)d_in[0];
    float* o = (float*)d_out;
    (void)in_sizes; (void)n_in; (void)out_size;

    cudaFuncSetAttribute(cmn_kernel,
                         cudaFuncAttributeMaxDynamicSharedMemorySize, (int)kRTb);
    cmn_kernel<<<kGrid, kF, kRTb>>>(x, o);
}

// round 6
// speedup vs baseline: 2.0357x; 1.1470x over previous
#include <cuda_runtime.h>
#include <cstdint>

// SlidingWindowCmn (16, 60000, 80) fp32, window=600, min=100, center=False,
// norm_vars=True.
// Distributed 16B cp.async -> 704-row SMEM ring (+8 mirror) -> per-thread
// sliding window (1 thread/feature). 16-row groups, wait_group 4 +
// __syncthreads per group. Lead = 5 groups (80 rows): cross-thread
// overwrite-safety requires lead*16 <= (704-601) - 15 = 88.

namespace {
constexpr int kB      = 16;
constexpr int kT      = 60000;
constexpr int kF      = 80;
constexpr int kWin    = 600;
constexpr int kMin    = 100;
constexpr int kChunks = 9;
constexpr int kL      = 6672;               // 8*6672 + 6624 = 60000
constexpr int kRL     = 704;                // logical ring rows (mult of 16)
constexpr int kRLf    = kRL * kF;           // 56320 floats
constexpr uint32_t kRLb = kRL * 320u;       // 225280 bytes (logical)
constexpr uint32_t kRTb = (kRL + 8) * 320u; // 227840 bytes (alloc, + mirror)
constexpr int kVO     = kRL - kWin - 1;     // 103 rows vn->vo slot distance
constexpr float kInvW = 1.0f / 601.0f;
constexpr int kGrid   = kB * kChunks;       // 144
}

__device__ __forceinline__ uint32_t smem_u32(const void* p) {
    uint32_t a;
    asm("{ .reg .u64 t; cvta.to.shared.u64 t, %1; cvt.u32.u64 %0, t; }"
        : "=r"(a) : "l"(p));
    return a;
}
__device__ __forceinline__ void cpa16(uint32_t s, const float* g) {
    asm volatile("cp.async.cg.shared.global [%0], [%1], 16;" :: "r"(s), "l"(g));
}
__device__ __forceinline__ void cpcommit() {
    asm volatile("cp.async.commit_group;" ::: "memory");
}
__device__ __forceinline__ void cpwait4() {
    asm volatile("cp.async.wait_group 4;" ::: "memory");
}

__global__ void __launch_bounds__(kF, 1)
cmn_kernel(const float* __restrict__ x, float* __restrict__ out)
{
    extern __shared__ float ring[];
    const int f = threadIdx.x;                    // feature 0..79
    const int c = blockIdx.x % kChunks;
    const int b = blockIdx.x / kChunks;

    const float* xb = x + (size_t)b * kT * kF;
    const int start = c * kL;
    const int end   = (c == kChunks - 1) ? kT : start + kL;

    const uint32_t rsb = smem_u32(ring);          // ring smem base (byte)
    const float* pClamp = x + ((size_t)kB * kT - 16) * kF;  // last full group

    int vnF;                 // consume group float-offset (slot*80)
    uint32_t issB;           // issue group byte-offset in ring
    const float* pIss;       // uniform group base pointer (no lane offset)

    if (c == 0) {
        vnF = 0; issB = 0;
        pIss = xb;
    } else {
        const int t0   = start - 608;             // 16-aligned; 7 pad + 601 warmup
        const int slot = t0 % kRL;                // multiple of 16
        vnF  = slot * kF;
        issB = (uint32_t)slot * 320u;
        pIss = xb + (size_t)t0 * kF;
    }

    auto issue16 = [&]() {
        const float* q  = (pIss > pClamp) ? pClamp : pIss;   // uniform clamp
        const float* qt = q + (f << 2);                      // thread's 16B lane
        const uint32_t a = rsb + issB + (uint32_t)(f << 4);
        cpa16(a,         qt);
        cpa16(a + 1280u, qt + 320);
        cpa16(a + 2560u, qt + 640);
        cpa16(a + 3840u, qt + 960);
        if (issB == 0) {                          // wrap group: fill mirror rows
            const uint32_t m = rsb + kRLb + (uint32_t)(f << 4);
            cpa16(m,         qt);
            cpa16(m + 1280u, qt + 320);
        }
        cpcommit();
        pIss += 16 * kF;
        issB += 5120u; if (issB == kRLb) issB = 0;
    };

    // prologue: 5 groups (80 rows) in flight
    #pragma unroll 1
    for (int g = 0; g < 5; ++g) issue16();

    float s = 0.f, ss = 0.f, mean, qss;
    float* po = out + (size_t)b * kT * kF + f;
    int nSteady;

    if (c == 0) {
        // groups 0..5: rows 0..95 accumulate
        #pragma unroll 1
        for (int g = 0; g < 6; ++g) {
            cpwait4(); __syncthreads();
            const float* rvn = ring + vnF + f;
            #pragma unroll
            for (int u = 0; u < 16; ++u) {
                float v = rvn[u * kF];
                s += v; ss = __fmaf_rn(v, v, ss);
            }
            vnF += 16 * kF;
            issue16();
        }
        // group 6: rows 96..111
        {
            cpwait4(); __syncthreads();
            const float* rvn = ring + vnF + f;
            #pragma unroll
            for (int u = 0; u < 4; ++u) {          // rows 96..99
                float v = rvn[u * kF];
                s += v; ss = __fmaf_rn(v, v, ss);
            }
            {   // burst-emit rows 0..99 with fixed n=100 stats
                const float inv = 1.0f / (float)kMin;
                const float m   = s * inv;
                const float var = __fmaf_rn(-m, m, ss * inv);
                const float r   = rsqrtf(var);
                #pragma unroll 4
                for (int t = 0; t < kMin; ++t) {
                    float v = ring[t * kF + f];
                    __stcs(po + t * kF, (v - m) * r);
                }
            }
            float n = 100.0f;
            #pragma unroll
            for (int u = 4; u < 16; ++u) {         // rows 100..111 growing
                float v = rvn[u * kF];
                s += v; ss = __fmaf_rn(v, v, ss);
                n += 1.0f;
                float inv = __fdividef(1.0f, n);
                float m   = s * inv;
                float var = __fmaf_rn(-m, m, ss * inv);
                __stcs(po + (96 + u) * kF, (v - m) * rsqrtf(var));
            }
            vnF += 16 * kF;
            issue16();
        }
        // groups 7..36: rows 112..591 growing
        po += 112 * kF;
        float n = 112.0f;
        #pragma unroll 1
        for (int g = 7; g < 37; ++g) {
            cpwait4(); __syncthreads();
            const float* rvn = ring + vnF + f;
            #pragma unroll
            for (int u = 0; u < 16; ++u) {
                float v = rvn[u * kF];
                s += v; ss = __fmaf_rn(v, v, ss);
                n += 1.0f;
                float inv = __fdividef(1.0f, n);
                float m   = s * inv;
                float var = __fmaf_rn(-m, m, ss * inv);
                __stcs(po + u * kF, (v - m) * rsqrtf(var));
            }
            vnF += 16 * kF;
            po  += 16 * kF;
            issue16();
        }
        // group 37: rows 592..607 (transition at t=600)
        {
            cpwait4(); __syncthreads();
            const float* rvn = ring + vnF + f;
            #pragma unroll
            for (int u = 0; u < 8; ++u) {          // rows 592..599 growing
                float v = rvn[u * kF];
                s += v; ss = __fmaf_rn(v, v, ss);
                n += 1.0f;
                float inv = __fdividef(1.0f, n);
                float m   = s * inv;
                float var = __fmaf_rn(-m, m, ss * inv);
                __stcs(po + u * kF, (v - m) * rsqrtf(var));
            }
            mean = s * kInvW; qss = ss * kInvW;
            #pragma unroll
            for (int u = 8; u < 16; ++u) {         // rows 600..607 steady
                float vn = rvn[u * kF];
                float vo = (u == 8) ? 0.0f : ring[(u - 9) * kF + f];
                float d  = vn - vo;
                float t1 = d * kInvW;
                mean += t1;
                qss   = __fmaf_rn(t1, vn + vo, qss);
                float var = __fmaf_rn(-mean, mean, qss);
                __stcs(po + u * kF, (vn - mean) * rsqrtf(var));
            }
            vnF += 16 * kF;                        // = 608*kF
            po  += 16 * kF;
            issue16();
        }
        nSteady = (kL - 608) / 16;                 // 379
    } else {
        // warmup group 0: rows t0+7 .. t0+15 (start-601 .. start-593)
        {
            cpwait4(); __syncthreads();
            const float* rvn = ring + vnF + f;
            #pragma unroll
            for (int u = 7; u < 16; ++u) {
                float v = rvn[u * kF];
                s += v; ss = __fmaf_rn(v, v, ss);
            }
            vnF += 16 * kF; if (vnF == kRLf) vnF = 0;
            issue16();
        }
        // warmup groups 1..37: 592 rows
        #pragma unroll 1
        for (int g = 1; g < 38; ++g) {
            cpwait4(); __syncthreads();
            const float* rvn = ring + vnF + f;
            #pragma unroll
            for (int u = 0; u < 16; ++u) {
                float v = rvn[u * kF];
                s += v; ss = __fmaf_rn(v, v, ss);
            }
            vnF += 16 * kF; if (vnF == kRLf) vnF = 0;
            issue16();
        }
        mean = s * kInvW; qss = ss * kInvW;
        po += (size_t)start * kF;
        nSteady = (end - start) / 16;              // 417 or 414
    }

    // ---- steady sliding loop ----
    #pragma unroll 1
    for (int g = 0; g < nSteady; ++g) {
        cpwait4(); __syncthreads();
        const float* rvn = ring + vnF + f;
        int voF = vnF + kVO * kF;                  // slot (t-601), group-aligned
        if (voF >= kRLf) voF -= kRLf;              // one wrap check / 16 rows
        const float* rvo = ring + voF + f;         // mirror covers straddle
        #pragma unroll
        for (int u = 0; u < 16; ++u) {
            float vn = rvn[u * kF];
            float vo = rvo[u * kF];
            float d  = vn - vo;
            float t1 = d * kInvW;
            mean += t1;
            qss   = __fmaf_rn(t1, vn + vo, qss);
            float var = __fmaf_rn(-mean, mean, qss);
            __stcs(po + u * kF, (vn - mean) * rsqrtf(var));
        }
        vnF += 16 * kF; if (vnF == kRLf) vnF = 0;
        po  += 16 * kF;
        issue16();
    }
}

extern "C" void kernel_launch(void* const* d_in, const int* in_sizes, int n_in,
                              void* d_out, int out_size)
{
    const float* x = (const float*)d_in[0];
    float* o = (float*)d_out;
    (void)in_sizes; (void)n_in; (void)out_size;

    cudaFuncSetAttribute(cmn_kernel,
                         cudaFuncAttributeMaxDynamicSharedMemorySize, (int)kRTb);
    cmn_kernel<<<kGrid, kF, kRTb>>>(x, o);
}